// round 11
// baseline (speedup 1.0000x reference)
#include <cuda_runtime.h>
#include <cstdint>

typedef unsigned long long u64;
typedef unsigned int u32;
typedef unsigned short u16;
#define DEV __device__ __forceinline__

// ---------------- global scratch: split + transposed bf16 weight planes [N][K] ----------------
__device__ __align__(256) u16 g_w1h[256 * 512];
__device__ __align__(256) u16 g_w1l[256 * 512];
__device__ __align__(256) u16 g_w2h[256 * 256];
__device__ __align__(256) u16 g_w2l[256 * 256];
__device__ __align__(256) u16 g_w3h[128 * 256];
__device__ __align__(256) u16 g_w3l[128 * 256];

// ================= PTX helpers (base ISA only) =================
DEV void cpa16(u32 s, const void* g) {
    asm volatile("cp.async.cg.shared.global [%0], [%1], 16;" :: "r"(s), "l"(g));
}
DEV void cpa_commit() { asm volatile("cp.async.commit_group;"); }
DEV void cpa_wait0()  { asm volatile("cp.async.wait_group 0;"); }

DEV u32 pack_bf16(float lo, float hi) {
    u32 r; asm("cvt.rn.bf16x2.f32 %0, %1, %2;" : "=r"(r) : "f"(hi), "f"(lo)); return r;
}
DEV u16 f2bf(float v) { u16 h; asm("cvt.rn.bf16.f32 %0, %1;" : "=h"(h) : "f"(v)); return h; }
DEV float bf2f(u16 u) { float f; asm("cvt.f32.bf16 %0, %1;" : "=f"(f) : "h"(u)); return f; }

DEV void mma16816(float* d, u32 a0, u32 a1, u32 a2, u32 a3, u32 b0, u32 b1) {
    asm volatile(
        "mma.sync.aligned.m16n8k16.row.col.f32.bf16.bf16.f32 "
        "{%0,%1,%2,%3}, {%4,%5,%6,%7}, {%8,%9}, {%0,%1,%2,%3};"
        : "+f"(d[0]), "+f"(d[1]), "+f"(d[2]), "+f"(d[3])
        : "r"(a0), "r"(a1), "r"(a2), "r"(a3), "r"(b0), "r"(b1));
}

// ================= weight split + transpose pre-kernel =================
__global__ void conv_w(const float* __restrict__ W1, const float* __restrict__ W2,
                       const float* __restrict__ W3)
{
    int idx = blockIdx.x * blockDim.x + threadIdx.x;
    int stride = gridDim.x * blockDim.x;
    for (int i = idx; i < 512 * 256; i += stride) {
        int k = i >> 8, n = i & 255;
        float v = W1[i];
        u16 h = f2bf(v);
        u16 l = f2bf(v - bf2f(h));
        g_w1h[n * 512 + k] = h;
        g_w1l[n * 512 + k] = l;
    }
    for (int i = idx; i < 256 * 256; i += stride) {
        int k = i >> 8, n = i & 255;
        float v = W2[i];
        u16 h = f2bf(v);
        u16 l = f2bf(v - bf2f(h));
        g_w2h[n * 256 + k] = h;
        g_w2l[n * 256 + k] = l;
    }
    for (int i = idx; i < 256 * 128; i += stride) {
        int k = i >> 7, n = i & 127;
        float v = W3[i];
        u16 h = f2bf(v);
        u16 l = f2bf(v - bf2f(h));
        g_w3h[n * 256 + k] = h;
        g_w3l[n * 256 + k] = l;
    }
}

// ================= geometry =================
constexpr int BATCH = 16384;
constexpr int BT    = 4;       // batches per CTA -> 48 rows
constexpr int MT    = 48;
constexpr int THREADS = 256;   // 8 warps: 1 M group x 8 N groups

constexpr int AFSTR = 264;     // full A plane row stride (u16), conflict-free fragments
constexpr int ASSTR = 24;      // layer-1 A slice row stride (16 k + pad)
constexpr int BSTR  = 24;      // B slice row stride (16 k + pad)

// smem layout (bytes)
constexpr int AF_HI = 0;                         // 48*264*2 = 25344
constexpr int AF_LO = 25344;                     // -> 50688
constexpr int AS_SZ = MT * ASSTR * 2;            // 2304 ; layer-1 slices alias AF region
constexpr int B_OFF = 50688;                     // B: [buf][plane] 256*24*2 = 12288 each
constexpr int B_PL  = 12288;
constexpr int B_BUF = 24576;
constexpr int HC_OFF = B_OFF;                    // fp32 scratch aliases B (48*70*4 = 13440)
constexpr int HCSTR  = 70;
constexpr int AM_OFF = B_OFF + 2 * B_BUF;        // 99840, 144 floats
constexpr int SMEM_BYTES = 100480;               // x2 CTAs = 200960 <= 227KB

// Fixed ECG graph neighbor lists (incl. self), 42 nonzeros of the 12x12 A_norm.
__device__ constexpr int NBR_OFF[13] = {0,5,11,16,20,23,26,28,31,34,37,40,42};
__device__ constexpr int NBR[42] = {
    0,1,2,3,4,
    0,1,2,3,4,5,
    0,1,2,3,5,
    0,1,2,3,
    0,1,4,
    1,2,5,
    6,7,
    6,7,8,
    7,8,9,
    8,9,10,
    9,10,11,
    10,11
};

// One KB=16 slab of the 3-term split GEMM (R7 fragment mapping, rb = 0).
template<int NT>
DEV void gemm_slab(const u16* Ah, const u16* Al, int astr,
                   const u16* Bh, const u16* Bl,
                   float acc[3][NT][4], int cb, int lane)
{
    const int lr = lane >> 2;
    const int lk = (lane & 3) * 2;
    u32 bh[NT][2], bl[NT][2];
    #pragma unroll
    for (int nt = 0; nt < NT; nt++) {
        int n = cb + nt * 8 + lr;
        bh[nt][0] = *(const u32*)(Bh + n * BSTR + lk);
        bh[nt][1] = *(const u32*)(Bh + n * BSTR + lk + 8);
        bl[nt][0] = *(const u32*)(Bl + n * BSTR + lk);
        bl[nt][1] = *(const u32*)(Bl + n * BSTR + lk + 8);
    }
    #pragma unroll
    for (int mt = 0; mt < 3; mt++) {
        int r = mt * 16 + lr;
        u32 a0h = *(const u32*)(Ah + r * astr + lk);
        u32 a1h = *(const u32*)(Ah + (r + 8) * astr + lk);
        u32 a2h = *(const u32*)(Ah + r * astr + lk + 8);
        u32 a3h = *(const u32*)(Ah + (r + 8) * astr + lk + 8);
        u32 a0l = *(const u32*)(Al + r * astr + lk);
        u32 a1l = *(const u32*)(Al + (r + 8) * astr + lk);
        u32 a2l = *(const u32*)(Al + r * astr + lk + 8);
        u32 a3l = *(const u32*)(Al + (r + 8) * astr + lk + 8);
        #pragma unroll
        for (int nt = 0; nt < NT; nt++) {
            mma16816(acc[mt][nt], a0h, a1h, a2h, a3h, bh[nt][0], bh[nt][1]);
            mma16816(acc[mt][nt], a0h, a1h, a2h, a3h, bl[nt][0], bl[nt][1]);
            mma16816(acc[mt][nt], a0l, a1l, a2l, a3l, bh[nt][0], bh[nt][1]);
        }
    }
}

// Dump D regs chunk-by-chunk (64 cols), A-mix + bias(+relu), write next-layer bf16
// A planes, or fused mean/max epilogue on the final layer.
template<int NT, bool FINAL>
DEV void readback(unsigned char* smem, float acc[3][NT][4],
                  const float* Am, const float* __restrict__ bias,
                  float* __restrict__ out, long long obase,
                  int tid, int lane, int cg)
{
    float* Hc = (float*)(smem + HC_OFF);
    u16* afh = (u16*)(smem + AF_HI);
    u16* afl = (u16*)(smem + AF_LO);
    #pragma unroll
    for (int ch = 0; ch < NT; ch++) {
        const bool active = (NT == 4) ? ((cg >> 1) == ch) : ((cg >> 2) == ch);
        const int lbase = (NT == 4) ? (cg & 1) * 32 : (cg & 3) * 16;
        if (active) {
            #pragma unroll
            for (int mt = 0; mt < 3; mt++) {
                int r = mt * 16 + (lane >> 2);
                #pragma unroll
                for (int nt = 0; nt < NT; nt++) {
                    int c = lbase + nt * 8 + (lane & 3) * 2;
                    *(float2*)(Hc + r * HCSTR + c) = make_float2(acc[mt][nt][0], acc[mt][nt][1]);
                    *(float2*)(Hc + (r + 8) * HCSTR + c) = make_float2(acc[mt][nt][2], acc[mt][nt][3]);
                }
            }
        }
        __syncthreads();
        {
            int b = tid & 3, c = tid >> 2;           // c: 0..63
            int col = ch * 64 + c;
            float h[12];
            #pragma unroll
            for (int l = 0; l < 12; l++) h[l] = Hc[(b * 12 + l) * HCSTR + c];
            float bv = __ldg(bias + col);
            if (!FINAL) {
                #pragma unroll
                for (int l = 0; l < 12; l++) {
                    float a = 0.f;
                    #pragma unroll
                    for (int q = NBR_OFF[l]; q < NBR_OFF[l + 1]; q++)
                        a += Am[l * 12 + NBR[q]] * h[NBR[q]];
                    float y = fmaxf(a + bv, 0.f);
                    int row = b * 12 + l;
                    u16 hb = f2bf(y);
                    afh[row * AFSTR + col] = hb;
                    afl[row * AFSTR + col] = f2bf(y - bf2f(hb));
                }
            } else {
                float sum = 0.f, mx = -3.402823466e38f;
                #pragma unroll
                for (int l = 0; l < 12; l++) {
                    float a = 0.f;
                    #pragma unroll
                    for (int q = NBR_OFF[l]; q < NBR_OFF[l + 1]; q++)
                        a += Am[l * 12 + NBR[q]] * h[NBR[q]];
                    float y = a + bv;
                    sum += y;
                    mx = fmaxf(mx, y);
                }
                float* op = out + (obase + b) * 256;
                op[col]       = sum * (1.0f / 12.0f);
                op[128 + col] = mx;
            }
        }
        __syncthreads();
    }
}

__global__ void __launch_bounds__(THREADS, 2)
ecg_mma(const float* __restrict__ x,
        const float* __restrict__ b1, const float* __restrict__ b2,
        const float* __restrict__ b3, float* __restrict__ out)
{
    extern __shared__ unsigned char smem[];
    float* Am = (float*)(smem + AM_OFF);
    const u32 smem_u = (u32)__cvta_generic_to_shared(smem);

    const int tid  = threadIdx.x;
    const int lane = tid & 31;
    const int w    = tid >> 5;       // 0..7 (N groups)
    const int cg   = w;
    const int cb   = cg * 32;        // N=256 layers
    const int cb3  = cg * 16;        // N=128 layer
    const long long rowbase = (long long)blockIdx.x * MT;
    const long long obase   = (long long)blockIdx.x * BT;

    if (tid == 0) {
        float a[12][12];
        for (int i = 0; i < 12; i++)
            for (int j = 0; j < 12; j++) a[i][j] = (i == j) ? 2.0f : 0.0f;
        const int ei[15] = {0,0,1,0,1,2,0,1,1,2,6,7,8,9,10};
        const int ej[15] = {1,2,2,3,3,3,4,4,5,5,7,8,9,10,11};
        for (int e = 0; e < 15; e++) { a[ei[e]][ej[e]] = 1.0f; a[ej[e]][ei[e]] = 1.0f; }
        float dinv[12];
        for (int i = 0; i < 12; i++) {
            float s = 0.f;
            for (int j = 0; j < 12; j++) s += a[i][j];
            dinv[i] = 1.0f / sqrtf(s);
        }
        for (int i = 0; i < 12; i++)
            for (int j = 0; j < 12; j++)
                Am[i * 12 + j] = dinv[i] * a[i][j] * dinv[j];
    }

    // staging roles
    // B (N=256): thread owns row bn=tid, 2 cpa16 per plane (32B of k)
    // B (N=128): bn3 = tid>>1 row, h3 = tid&1 half, 1 cpa16 per plane
    const int bn3 = tid >> 1, h3 = tid & 1;
    // layer-1 A: row xr = tid>>2 (active <48), k-quarter xq = tid&3 (4 k each)
    const int xr = tid >> 2, xq = tid & 3;
    const bool xact = tid < MT * 4;   // 192

    u16* ashi[2] = {(u16*)(smem + 0),              (u16*)(smem + 2 * AS_SZ)};
    u16* aslo[2] = {(u16*)(smem + AS_SZ),          (u16*)(smem + 3 * AS_SZ)};
    u16* bshi[2] = {(u16*)(smem + B_OFF),          (u16*)(smem + B_OFF + B_BUF)};
    u16* bslo[2] = {(u16*)(smem + B_OFF + B_PL),   (u16*)(smem + B_OFF + B_BUF + B_PL)};
    const u32 b_u = smem_u + B_OFF;

    float acc[3][4][4];
    #pragma unroll
    for (int i = 0; i < 3; i++)
        #pragma unroll
        for (int j = 0; j < 4; j++)
            #pragma unroll
            for (int v = 0; v < 4; v++) acc[i][j][v] = 0.f;

    // ---------------- Layer 1: X(48x512) @ W1 (K=512, 32 slabs of 16) ----------------
    {
        // preload slab 0
        cpa16(b_u + tid * 48,            (const char*)(g_w1h + tid * 512));
        cpa16(b_u + tid * 48 + 16,       (const char*)(g_w1h + tid * 512 + 8));
        cpa16(b_u + B_PL + tid * 48,     (const char*)(g_w1l + tid * 512));
        cpa16(b_u + B_PL + tid * 48 + 16,(const char*)(g_w1l + tid * 512 + 8));
        cpa_commit();
        if (xact) {
            float4 v = *(const float4*)(x + (rowbase + xr) * 512 + xq * 4);
            u32 h0 = pack_bf16(v.x, v.y);
            u32 h1 = pack_bf16(v.z, v.w);
            *(u32*)(ashi[0] + xr * ASSTR + xq * 4)     = h0;
            *(u32*)(ashi[0] + xr * ASSTR + xq * 4 + 2) = h1;
            *(u32*)(aslo[0] + xr * ASSTR + xq * 4) =
                pack_bf16(v.x - bf2f((u16)(h0 & 0xFFFF)), v.y - bf2f((u16)(h0 >> 16)));
            *(u32*)(aslo[0] + xr * ASSTR + xq * 4 + 2) =
                pack_bf16(v.z - bf2f((u16)(h1 & 0xFFFF)), v.w - bf2f((u16)(h1 >> 16)));
        }
        cpa_wait0();
        __syncthreads();

        for (int it = 0; it < 32; it++) {
            const int cur = it & 1, nxt = cur ^ 1;
            const bool more = it < 31;
            float4 v;
            if (more) {
                const int kb = (it + 1) * 16;
                const u32 bb = b_u + nxt * B_BUF;
                cpa16(bb + tid * 48,            (const char*)(g_w1h + tid * 512 + kb));
                cpa16(bb + tid * 48 + 16,       (const char*)(g_w1h + tid * 512 + kb + 8));
                cpa16(bb + B_PL + tid * 48,     (const char*)(g_w1l + tid * 512 + kb));
                cpa16(bb + B_PL + tid * 48 + 16,(const char*)(g_w1l + tid * 512 + kb + 8));
                cpa_commit();
                if (xact)
                    v = *(const float4*)(x + (rowbase + xr) * 512 + kb + xq * 4);
            }
            gemm_slab<4>(ashi[cur], aslo[cur], ASSTR, bshi[cur], bslo[cur], acc, cb, lane);
            if (more) {
                if (xact) {
                    u32 h0 = pack_bf16(v.x, v.y);
                    u32 h1 = pack_bf16(v.z, v.w);
                    *(u32*)(ashi[nxt] + xr * ASSTR + xq * 4)     = h0;
                    *(u32*)(ashi[nxt] + xr * ASSTR + xq * 4 + 2) = h1;
                    *(u32*)(aslo[nxt] + xr * ASSTR + xq * 4) =
                        pack_bf16(v.x - bf2f((u16)(h0 & 0xFFFF)), v.y - bf2f((u16)(h0 >> 16)));
                    *(u32*)(aslo[nxt] + xr * ASSTR + xq * 4 + 2) =
                        pack_bf16(v.z - bf2f((u16)(h1 & 0xFFFF)), v.w - bf2f((u16)(h1 >> 16)));
                }
                cpa_wait0();
            }
            __syncthreads();
        }
    }
    readback<4, false>(smem, acc, Am, b1, out, obase, tid, lane, cg);

    // ---------------- Layer 2: H1(48x256) @ W2 (K=256, 16 slabs) ----------------
    #pragma unroll
    for (int i = 0; i < 3; i++)
        #pragma unroll
        for (int j = 0; j < 4; j++)
            #pragma unroll
            for (int v = 0; v < 4; v++) acc[i][j][v] = 0.f;
    {
        u16* afh = (u16*)(smem + AF_HI);
        u16* afl = (u16*)(smem + AF_LO);
        cpa16(b_u + tid * 48,            (const char*)(g_w2h + tid * 256));
        cpa16(b_u + tid * 48 + 16,       (const char*)(g_w2h + tid * 256 + 8));
        cpa16(b_u + B_PL + tid * 48,     (const char*)(g_w2l + tid * 256));
        cpa16(b_u + B_PL + tid * 48 + 16,(const char*)(g_w2l + tid * 256 + 8));
        cpa_commit();
        cpa_wait0();
        __syncthreads();
        for (int it = 0; it < 16; it++) {
            const int cur = it & 1, nxt = cur ^ 1;
            const bool more = it < 15;
            if (more) {
                const int kb = (it + 1) * 16;
                const u32 bb = b_u + nxt * B_BUF;
                cpa16(bb + tid * 48,            (const char*)(g_w2h + tid * 256 + kb));
                cpa16(bb + tid * 48 + 16,       (const char*)(g_w2h + tid * 256 + kb + 8));
                cpa16(bb + B_PL + tid * 48,     (const char*)(g_w2l + tid * 256 + kb));
                cpa16(bb + B_PL + tid * 48 + 16,(const char*)(g_w2l + tid * 256 + kb + 8));
                cpa_commit();
            }
            gemm_slab<4>(afh + it * 16, afl + it * 16, AFSTR, bshi[cur], bslo[cur], acc, cb, lane);
            if (more) cpa_wait0();
            __syncthreads();
        }
    }
    readback<4, false>(smem, acc, Am, b2, out, obase, tid, lane, cg);

    // ---------------- Layer 3: H2(48x256) @ W3 (K=256, 16 slabs, N=128) ----------------
    float acc3[3][2][4];
    #pragma unroll
    for (int i = 0; i < 3; i++)
        #pragma unroll
        for (int j = 0; j < 2; j++)
            #pragma unroll
            for (int v = 0; v < 4; v++) acc3[i][j][v] = 0.f;
    {
        u16* afh = (u16*)(smem + AF_HI);
        u16* afl = (u16*)(smem + AF_LO);
        cpa16(b_u + bn3 * 48 + h3 * 16,        (const char*)(g_w3h + bn3 * 256 + h3 * 8));
        cpa16(b_u + B_PL + bn3 * 48 + h3 * 16, (const char*)(g_w3l + bn3 * 256 + h3 * 8));
        cpa_commit();
        cpa_wait0();
        __syncthreads();
        for (int it = 0; it < 16; it++) {
            const int cur = it & 1, nxt = cur ^ 1;
            const bool more = it < 15;
            if (more) {
                const int kb = (it + 1) * 16;
                const u32 bb = b_u + nxt * B_BUF;
                cpa16(bb + bn3 * 48 + h3 * 16,        (const char*)(g_w3h + bn3 * 256 + kb + h3 * 8));
                cpa16(bb + B_PL + bn3 * 48 + h3 * 16, (const char*)(g_w3l + bn3 * 256 + kb + h3 * 8));
                cpa_commit();
            }
            gemm_slab<2>(afh + it * 16, afl + it * 16, AFSTR, bshi[cur], bslo[cur], acc3, cb3, lane);
            if (more) cpa_wait0();
            __syncthreads();
        }
    }
    readback<2, true>(smem, acc3, Am, b3, out, obase, tid, lane, cg);
}

extern "C" void kernel_launch(void* const* d_in, const int* in_sizes, int n_in,
                              void* d_out, int out_size)
{
    const float* x  = (const float*)d_in[0];
    const float* W1 = (const float*)d_in[1];
    const float* b1 = (const float*)d_in[2];
    const float* W2 = (const float*)d_in[3];
    const float* b2 = (const float*)d_in[4];
    const float* W3 = (const float*)d_in[5];
    const float* b3 = (const float*)d_in[6];
    float* out = (float*)d_out;

    conv_w<<<148, 512>>>(W1, W2, W3);

    cudaFuncSetAttribute(ecg_mma, cudaFuncAttributeMaxDynamicSharedMemorySize, SMEM_BYTES);
    ecg_mma<<<BATCH / BT, THREADS, SMEM_BYTES>>>(x, b1, b2, b3, out);
}

// round 12
// speedup vs baseline: 1.8646x; 1.8646x over previous
#include <cuda_runtime.h>
#include <cstdint>

typedef unsigned long long u64;
typedef unsigned int u32;
typedef unsigned short u16;
#define DEV __device__ __forceinline__

// ---------------- global scratch: fragment-major bf16 weight planes [K/16][N][16perm] ----------------
__device__ __align__(256) u16 g_w1h[512 * 256];
__device__ __align__(256) u16 g_w1l[512 * 256];
__device__ __align__(256) u16 g_w2h[256 * 256];
__device__ __align__(256) u16 g_w2l[256 * 256];
__device__ __align__(256) u16 g_w3h[256 * 128];
__device__ __align__(256) u16 g_w3l[256 * 128];

// ================= PTX helpers =================
DEV u32 pack_bf16(float lo, float hi) {
    u32 r; asm("cvt.rn.bf16x2.f32 %0, %1, %2;" : "=r"(r) : "f"(hi), "f"(lo)); return r;
}
DEV u16 f2bf(float v) { u16 h; asm("cvt.rn.bf16.f32 %0, %1;" : "=h"(h) : "f"(v)); return h; }
DEV float bf2f(u16 u) { float f; asm("cvt.f32.bf16 %0, %1;" : "=f"(f) : "h"(u)); return f; }

DEV void mma16816(float* d, u32 a0, u32 a1, u32 a2, u32 a3, u32 b0, u32 b1) {
    asm volatile(
        "mma.sync.aligned.m16n8k16.row.col.f32.bf16.bf16.f32 "
        "{%0,%1,%2,%3}, {%4,%5,%6,%7}, {%8,%9}, {%0,%1,%2,%3};"
        : "+f"(d[0]), "+f"(d[1]), "+f"(d[2]), "+f"(d[3])
        : "r"(a0), "r"(a1), "r"(a2), "r"(a3), "r"(b0), "r"(b1));
}

// position of k (0..15) in fragment-major order [0,1,8,9, 2,3,10,11, 4,5,12,13, 6,7,14,15]
DEV int kpos(int k) {
    return (k & 1) | (((k >> 3) & 1) << 1) | (((k >> 1) & 3) << 2);
}

// ================= weight split + fragment-pack pre-kernel =================
__global__ void conv_w(const float* __restrict__ W1, const float* __restrict__ W2,
                       const float* __restrict__ W3)
{
    int idx = blockIdx.x * blockDim.x + threadIdx.x;
    int stride = gridDim.x * blockDim.x;
    for (int i = idx; i < 512 * 256; i += stride) {
        int k = i >> 8, n = i & 255;
        float v = W1[i];
        u16 h = f2bf(v);
        u16 l = f2bf(v - bf2f(h));
        int d = (((k >> 4) * 256 + n) << 4) + kpos(k & 15);
        g_w1h[d] = h; g_w1l[d] = l;
    }
    for (int i = idx; i < 256 * 256; i += stride) {
        int k = i >> 8, n = i & 255;
        float v = W2[i];
        u16 h = f2bf(v);
        u16 l = f2bf(v - bf2f(h));
        int d = (((k >> 4) * 256 + n) << 4) + kpos(k & 15);
        g_w2h[d] = h; g_w2l[d] = l;
    }
    for (int i = idx; i < 256 * 128; i += stride) {
        int k = i >> 7, n = i & 127;
        float v = W3[i];
        u16 h = f2bf(v);
        u16 l = f2bf(v - bf2f(h));
        int d = (((k >> 4) * 128 + n) << 4) + kpos(k & 15);
        g_w3h[d] = h; g_w3l[d] = l;
    }
}

// ================= geometry =================
constexpr int BATCH = 16384;
constexpr int BT    = 8;
constexpr int MT    = 96;
constexpr int THREADS = 512;

constexpr int AFSTR = 264;   // full A plane row stride (u16), conflict-free
constexpr int ASSTR = 40;    // layer-1 A slice row stride (32 k + pad)

// smem layout (bytes)
constexpr int AF_HI = 0;                         // 96*264*2 = 50688
constexpr int AF_LO = 50688;                     // -> 101376
constexpr int AS_SZ = MT * ASSTR * 2;            // 7680; layer-1 slices alias AF region
constexpr int HC_OFF = 101376;                   // fp32 scratch 96*70*4 = 26880
constexpr int HCSTR  = 70;
constexpr int AM_OFF = 128256;                   // 144 floats
constexpr int SMEM_BYTES = 129024;

// Fixed ECG graph neighbor lists (incl. self), 42 nonzeros of the 12x12 A_norm.
__device__ constexpr int NBR_OFF[13] = {0,5,11,16,20,23,26,28,31,34,37,40,42};
__device__ constexpr int NBR[42] = {
    0,1,2,3,4,
    0,1,2,3,4,5,
    0,1,2,3,5,
    0,1,2,3,
    0,1,4,
    1,2,5,
    6,7,
    6,7,8,
    7,8,9,
    8,9,10,
    9,10,11,
    10,11
};

// One 16-k chunk of the 3-term split GEMM.
// A: [96][astr] u16 smem planes (linear k). B: fragment-major GLOBAL planes,
// bph/bpl pre-offset to (kc*N + cb + lr)*16 + 4q; nt stride = 128 u16 (8 n).
template<int NT>
DEV void gemm_chunk(const u16* Ah, const u16* Al, int astr, int a_kof, int rb,
                    const u16* bph, const u16* bpl,
                    float acc[3][NT][4], int lane)
{
    u64 bhv[NT], blv[NT];
    #pragma unroll
    for (int nt = 0; nt < NT; nt++) {
        bhv[nt] = *(const u64*)(bph + (nt << 7));
        blv[nt] = *(const u64*)(bpl + (nt << 7));
    }
    const int lr = lane >> 2;
    const int lk = a_kof + (lane & 3) * 2;
    #pragma unroll
    for (int mt = 0; mt < 3; mt++) {
        int r = rb + mt * 16 + lr;
        u32 a0h = *(const u32*)(Ah + r * astr + lk);
        u32 a1h = *(const u32*)(Ah + (r + 8) * astr + lk);
        u32 a2h = *(const u32*)(Ah + r * astr + lk + 8);
        u32 a3h = *(const u32*)(Ah + (r + 8) * astr + lk + 8);
        u32 a0l = *(const u32*)(Al + r * astr + lk);
        u32 a1l = *(const u32*)(Al + (r + 8) * astr + lk);
        u32 a2l = *(const u32*)(Al + r * astr + lk + 8);
        u32 a3l = *(const u32*)(Al + (r + 8) * astr + lk + 8);
        #pragma unroll
        for (int nt = 0; nt < NT; nt++) {
            u32 b0 = (u32)bhv[nt], b1 = (u32)(bhv[nt] >> 32);
            u32 c0 = (u32)blv[nt], c1 = (u32)(blv[nt] >> 32);
            mma16816(acc[mt][nt], a0h, a1h, a2h, a3h, b0, b1);
            mma16816(acc[mt][nt], a0h, a1h, a2h, a3h, c0, c1);
            mma16816(acc[mt][nt], a0l, a1l, a2l, a3l, b0, b1);
        }
    }
}

// Dump D regs chunk-by-chunk, A-mix + bias(+relu), write next-layer bf16 A planes
// (or fused mean/max epilogue on the final layer).
template<int NT, bool FINAL>
DEV void readback(unsigned char* smem, float acc[3][NT][4],
                  const float* Am, const float* __restrict__ bias,
                  float* __restrict__ out, long long obase,
                  int tid, int lane, int rg, int cg)
{
    float* Hc = (float*)(smem + HC_OFF);
    u16* afh = (u16*)(smem + AF_HI);
    u16* afl = (u16*)(smem + AF_LO);
    #pragma unroll
    for (int ch = 0; ch < NT; ch++) {
        const bool active = (NT == 4) ? ((cg >> 1) == ch) : ((cg >> 2) == ch);
        const int lbase = (NT == 4) ? (cg & 1) * 32 : (cg & 3) * 16;
        if (active) {
            #pragma unroll
            for (int mt = 0; mt < 3; mt++) {
                int r = rg * 48 + mt * 16 + (lane >> 2);
                #pragma unroll
                for (int nt = 0; nt < NT; nt++) {
                    int c = lbase + nt * 8 + (lane & 3) * 2;
                    *(float2*)(Hc + r * HCSTR + c) = make_float2(acc[mt][nt][0], acc[mt][nt][1]);
                    *(float2*)(Hc + (r + 8) * HCSTR + c) = make_float2(acc[mt][nt][2], acc[mt][nt][3]);
                }
            }
        }
        __syncthreads();
        if (!FINAL) {
            if (tid < 256) {
                int b = tid & 7, cp = tid >> 3;        // cp: 0..31 column pairs
                float h0[12], h1[12];
                #pragma unroll
                for (int l = 0; l < 12; l++) {
                    float2 v = *(const float2*)(Hc + (b * 12 + l) * HCSTR + cp * 2);
                    h0[l] = v.x; h1[l] = v.y;
                }
                int k0 = ch * 64 + cp * 2;
                float bv0 = __ldg(bias + k0), bv1 = __ldg(bias + k0 + 1);
                #pragma unroll
                for (int l = 0; l < 12; l++) {
                    float a0 = 0.f, a1 = 0.f;
                    #pragma unroll
                    for (int q = NBR_OFF[l]; q < NBR_OFF[l + 1]; q++) {
                        int m = NBR[q];
                        float w = Am[l * 12 + m];
                        a0 += w * h0[m];
                        a1 += w * h1[m];
                    }
                    float y0 = fmaxf(a0 + bv0, 0.f);
                    float y1 = fmaxf(a1 + bv1, 0.f);
                    int row = b * 12 + l;
                    u32 hiw = pack_bf16(y0, y1);
                    *(u32*)(afh + row * AFSTR + k0) = hiw;
                    float r0 = bf2f((u16)(hiw & 0xFFFF));
                    float r1 = bf2f((u16)(hiw >> 16));
                    *(u32*)(afl + row * AFSTR + k0) = pack_bf16(y0 - r0, y1 - r1);
                }
            }
        } else {
            int b = tid & 7, c = tid >> 3;             // c: 0..63
            int col = ch * 64 + c;
            float h[12];
            #pragma unroll
            for (int l = 0; l < 12; l++) h[l] = Hc[(b * 12 + l) * HCSTR + c];
            float bv = __ldg(bias + col);
            float sum = 0.f, mx = -3.402823466e38f;
            #pragma unroll
            for (int l = 0; l < 12; l++) {
                float a = 0.f;
                #pragma unroll
                for (int q = NBR_OFF[l]; q < NBR_OFF[l + 1]; q++)
                    a += Am[l * 12 + NBR[q]] * h[NBR[q]];
                float y = a + bv;
                sum += y;
                mx = fmaxf(mx, y);
            }
            float* op = out + (obase + b) * 256;
            op[col]       = sum * (1.0f / 12.0f);
            op[128 + col] = mx;
        }
        __syncthreads();
    }
}

__global__ void __launch_bounds__(THREADS, 1)
ecg_mma(const float* __restrict__ x,
        const float* __restrict__ b1, const float* __restrict__ b2,
        const float* __restrict__ b3, float* __restrict__ out)
{
    extern __shared__ unsigned char smem[];
    float* Am = (float*)(smem + AM_OFF);

    const int tid  = threadIdx.x;
    const int lane = tid & 31;
    const int w    = tid >> 5;       // 0..15
    const int rg   = w >> 3;         // 0..1 (M group)
    const int cg   = w & 7;          // 0..7 (N group)
    const int rb   = rg * 48;
    const int cb   = cg * 32;        // N=256 layers
    const int cb3  = cg * 16;        // N=128 layer
    const int lr   = lane >> 2;
    const int q    = lane & 3;
    const long long rowbase = (long long)blockIdx.x * MT;
    const long long obase   = (long long)blockIdx.x * BT;

    if (tid == 0) {
        float a[12][12];
        for (int i = 0; i < 12; i++)
            for (int j = 0; j < 12; j++) a[i][j] = (i == j) ? 2.0f : 0.0f;
        const int ei[15] = {0,0,1,0,1,2,0,1,1,2,6,7,8,9,10};
        const int ej[15] = {1,2,2,3,3,3,4,4,5,5,7,8,9,10,11};
        for (int e = 0; e < 15; e++) { a[ei[e]][ej[e]] = 1.0f; a[ej[e]][ei[e]] = 1.0f; }
        float dinv[12];
        for (int i = 0; i < 12; i++) {
            float s = 0.f;
            for (int j = 0; j < 12; j++) s += a[i][j];
            dinv[i] = 1.0f / sqrtf(s);
        }
        for (int i = 0; i < 12; i++)
            for (int j = 0; j < 12; j++)
                Am[i * 12 + j] = dinv[i] * a[i][j] * dinv[j];
    }

    // per-warp B fragment base offsets (u16 units): (cb + lr)*16 + 4q
    const u16* bph1 = g_w1h + ((cb  + lr) << 4) + (q << 2);
    const u16* bpl1 = g_w1l + ((cb  + lr) << 4) + (q << 2);
    const u16* bph2 = g_w2h + ((cb  + lr) << 4) + (q << 2);
    const u16* bpl2 = g_w2l + ((cb  + lr) << 4) + (q << 2);
    const u16* bph3 = g_w3h + ((cb3 + lr) << 4) + (q << 2);
    const u16* bpl3 = g_w3l + ((cb3 + lr) << 4) + (q << 2);
    constexpr int KSTEP256 = 256 * 16;   // u16 per 16-k chunk, N=256
    constexpr int KSTEP128 = 128 * 16;   // N=128

    // layer-1 A staging: row xr (active <96), k-quarter xq (8 floats each)
    const int xr = tid >> 2, xq = tid & 3;
    const bool xact = tid < MT * 4;

    u16* ashi[2] = {(u16*)(smem + 0),      (u16*)(smem + 2 * AS_SZ)};
    u16* aslo[2] = {(u16*)(smem + AS_SZ),  (u16*)(smem + 3 * AS_SZ)};

    float acc[3][4][4];
    #pragma unroll
    for (int i = 0; i < 3; i++)
        #pragma unroll
        for (int j = 0; j < 4; j++)
            #pragma unroll
            for (int v = 0; v < 4; v++) acc[i][j][v] = 0.f;

    // ---------------- Layer 1: X(96x512) @ W1 (K=512, 16 slabs of 32) ----------------
    {
        if (xact) {
            float4 v0 = *(const float4*)(x + (rowbase + xr) * 512 + xq * 8);
            float4 v1 = *(const float4*)(x + (rowbase + xr) * 512 + xq * 8 + 4);
            float vals[8] = {v0.x,v0.y,v0.z,v0.w, v1.x,v1.y,v1.z,v1.w};
            #pragma unroll
            for (int i = 0; i < 4; i++) {
                u32 hiw = pack_bf16(vals[2*i], vals[2*i+1]);
                *(u32*)(ashi[0] + xr * ASSTR + xq * 8 + 2 * i) = hiw;
                float r0 = bf2f((u16)(hiw & 0xFFFF));
                float r1 = bf2f((u16)(hiw >> 16));
                *(u32*)(aslo[0] + xr * ASSTR + xq * 8 + 2 * i) = pack_bf16(vals[2*i] - r0, vals[2*i+1] - r1);
            }
        }
        __syncthreads();

        for (int it = 0; it < 16; it++) {
            const int cur = it & 1, nxt = cur ^ 1;
            const bool more = it < 15;
            float4 v0, v1;
            if (more && xact) {
                v0 = *(const float4*)(x + (rowbase + xr) * 512 + (it + 1) * 32 + xq * 8);
                v1 = *(const float4*)(x + (rowbase + xr) * 512 + (it + 1) * 32 + xq * 8 + 4);
            }
            gemm_chunk<4>(ashi[cur], aslo[cur], ASSTR, 0, rb,
                          bph1 + (2 * it) * KSTEP256, bpl1 + (2 * it) * KSTEP256, acc, lane);
            gemm_chunk<4>(ashi[cur], aslo[cur], ASSTR, 16, rb,
                          bph1 + (2 * it + 1) * KSTEP256, bpl1 + (2 * it + 1) * KSTEP256, acc, lane);
            if (more && xact) {
                float vals[8] = {v0.x,v0.y,v0.z,v0.w, v1.x,v1.y,v1.z,v1.w};
                #pragma unroll
                for (int i = 0; i < 4; i++) {
                    u32 hiw = pack_bf16(vals[2*i], vals[2*i+1]);
                    *(u32*)(ashi[nxt] + xr * ASSTR + xq * 8 + 2 * i) = hiw;
                    float r0 = bf2f((u16)(hiw & 0xFFFF));
                    float r1 = bf2f((u16)(hiw >> 16));
                    *(u32*)(aslo[nxt] + xr * ASSTR + xq * 8 + 2 * i) = pack_bf16(vals[2*i] - r0, vals[2*i+1] - r1);
                }
            }
            __syncthreads();
        }
    }
    readback<4, false>(smem, acc, Am, b1, out, obase, tid, lane, rg, cg);

    // ---------------- Layer 2: H1(96x256) @ W2 (K=256, 16 chunks, NO barriers) ----------------
    #pragma unroll
    for (int i = 0; i < 3; i++)
        #pragma unroll
        for (int j = 0; j < 4; j++)
            #pragma unroll
            for (int v = 0; v < 4; v++) acc[i][j][v] = 0.f;
    {
        u16* afh = (u16*)(smem + AF_HI);
        u16* afl = (u16*)(smem + AF_LO);
        #pragma unroll 2
        for (int kc = 0; kc < 16; kc++)
            gemm_chunk<4>(afh, afl, AFSTR, kc * 16, rb,
                          bph2 + kc * KSTEP256, bpl2 + kc * KSTEP256, acc, lane);
    }
    readback<4, false>(smem, acc, Am, b2, out, obase, tid, lane, rg, cg);

    // ---------------- Layer 3: H2(96x256) @ W3 (K=256, 16 chunks, N=128, NO barriers) ----------------
    float acc3[3][2][4];
    #pragma unroll
    for (int i = 0; i < 3; i++)
        #pragma unroll
        for (int j = 0; j < 2; j++)
            #pragma unroll
            for (int v = 0; v < 4; v++) acc3[i][j][v] = 0.f;
    {
        u16* afh = (u16*)(smem + AF_HI);
        u16* afl = (u16*)(smem + AF_LO);
        #pragma unroll 2
        for (int kc = 0; kc < 16; kc++)
            gemm_chunk<2>(afh, afl, AFSTR, kc * 16, rb,
                          bph3 + kc * KSTEP128, bpl3 + kc * KSTEP128, acc3, lane);
    }
    readback<2, true>(smem, acc3, Am, b3, out, obase, tid, lane, rg, cg);
}

extern "C" void kernel_launch(void* const* d_in, const int* in_sizes, int n_in,
                              void* d_out, int out_size)
{
    const float* x  = (const float*)d_in[0];
    const float* W1 = (const float*)d_in[1];
    const float* b1 = (const float*)d_in[2];
    const float* W2 = (const float*)d_in[3];
    const float* b2 = (const float*)d_in[4];
    const float* W3 = (const float*)d_in[5];
    const float* b3 = (const float*)d_in[6];
    float* out = (float*)d_out;

    conv_w<<<148, 512>>>(W1, W2, W3);

    cudaFuncSetAttribute(ecg_mma, cudaFuncAttributeMaxDynamicSharedMemorySize, SMEM_BYTES);
    ecg_mma<<<BATCH / BT, THREADS, SMEM_BYTES>>>(x, b1, b2, b3, out);
}

// round 13
// speedup vs baseline: 1.9027x; 1.0204x over previous
#include <cuda_runtime.h>
#include <cstdint>

typedef unsigned long long u64;
typedef unsigned int u32;
typedef unsigned short u16;
#define DEV __device__ __forceinline__

// ---------------- global scratch: fragment-major bf16 weight planes [K/16][N][16perm] ----------------
__device__ __align__(256) u16 g_w1h[512 * 256];
__device__ __align__(256) u16 g_w1l[512 * 256];
__device__ __align__(256) u16 g_w2h[256 * 256];
__device__ __align__(256) u16 g_w2l[256 * 256];
__device__ __align__(256) u16 g_w3h[256 * 128];
__device__ __align__(256) u16 g_w3l[256 * 128];

// ================= PTX helpers =================
DEV u32 pack_bf16(float lo, float hi) {
    u32 r; asm("cvt.rn.bf16x2.f32 %0, %1, %2;" : "=r"(r) : "f"(hi), "f"(lo)); return r;
}
DEV u16 f2bf(float v) { u16 h; asm("cvt.rn.bf16.f32 %0, %1;" : "=h"(h) : "f"(v)); return h; }
DEV float bf2f(u16 u) { float f; asm("cvt.f32.bf16 %0, %1;" : "=f"(f) : "h"(u)); return f; }

DEV void mma16816(float* d, u32 a0, u32 a1, u32 a2, u32 a3, u32 b0, u32 b1) {
    asm volatile(
        "mma.sync.aligned.m16n8k16.row.col.f32.bf16.bf16.f32 "
        "{%0,%1,%2,%3}, {%4,%5,%6,%7}, {%8,%9}, {%0,%1,%2,%3};"
        : "+f"(d[0]), "+f"(d[1]), "+f"(d[2]), "+f"(d[3])
        : "r"(a0), "r"(a1), "r"(a2), "r"(a3), "r"(b0), "r"(b1));
}

// position of k (0..15) in fragment-major order [0,1,8,9, 2,3,10,11, 4,5,12,13, 6,7,14,15]
DEV int kpos(int k) {
    return (k & 1) | (((k >> 3) & 1) << 1) | (((k >> 1) & 3) << 2);
}

// ================= weight split + fragment-pack pre-kernel =================
__global__ void conv_w(const float* __restrict__ W1, const float* __restrict__ W2,
                       const float* __restrict__ W3)
{
    int idx = blockIdx.x * blockDim.x + threadIdx.x;
    int stride = gridDim.x * blockDim.x;
    for (int i = idx; i < 512 * 256; i += stride) {
        int k = i >> 8, n = i & 255;
        float v = W1[i];
        u16 h = f2bf(v);
        u16 l = f2bf(v - bf2f(h));
        int d = (((k >> 4) * 256 + n) << 4) + kpos(k & 15);
        g_w1h[d] = h; g_w1l[d] = l;
    }
    for (int i = idx; i < 256 * 256; i += stride) {
        int k = i >> 8, n = i & 255;
        float v = W2[i];
        u16 h = f2bf(v);
        u16 l = f2bf(v - bf2f(h));
        int d = (((k >> 4) * 256 + n) << 4) + kpos(k & 15);
        g_w2h[d] = h; g_w2l[d] = l;
    }
    for (int i = idx; i < 256 * 128; i += stride) {
        int k = i >> 7, n = i & 127;
        float v = W3[i];
        u16 h = f2bf(v);
        u16 l = f2bf(v - bf2f(h));
        int d = (((k >> 4) * 128 + n) << 4) + kpos(k & 15);
        g_w3h[d] = h; g_w3l[d] = l;
    }
}

// ================= geometry =================
constexpr int BATCH = 16384;
constexpr int BT    = 8;
constexpr int MT    = 96;
constexpr int THREADS = 512;

constexpr int AFSTR = 264;   // full A plane row stride (u16), conflict-free
constexpr int ASSTR = 40;    // layer-1 A slice row stride (32 k + pad)

// smem layout (bytes)
constexpr int AF_HI = 0;                         // 96*264*2 = 50688
constexpr int AF_LO = 50688;                     // -> 101376
constexpr int AS_SZ = MT * ASSTR * 2;            // 7680; layer-1 slices alias AF region
constexpr int HC_OFF = 101376;                   // fp32 scratch 96*264*4 = 101376 (full width)
constexpr int HCSTR  = 264;                      // floats; banks (4*lr+q) conflict-free
constexpr int AM_OFF = 202752;                   // 144 floats
constexpr int SMEM_BYTES = 203392;

// Fixed ECG graph neighbor lists (incl. self), 42 nonzeros of the 12x12 A_norm.
__device__ constexpr int NBR_OFF[13] = {0,5,11,16,20,23,26,28,31,34,37,40,42};
__device__ constexpr int NBR[42] = {
    0,1,2,3,4,
    0,1,2,3,4,5,
    0,1,2,3,5,
    0,1,2,3,
    0,1,4,
    1,2,5,
    6,7,
    6,7,8,
    7,8,9,
    8,9,10,
    9,10,11,
    10,11
};

// One 16-k chunk of the 3-term split GEMM.
// A: [96][astr] u16 smem planes (linear k). B: fragment-major GLOBAL planes,
// bph/bpl pre-offset to (kc*N + cb + lr)*16 + 4q; nt stride = 128 u16 (8 n).
template<int NT>
DEV void gemm_chunk(const u16* Ah, const u16* Al, int astr, int a_kof, int rb,
                    const u16* bph, const u16* bpl,
                    float acc[3][NT][4], int lane)
{
    u64 bhv[NT], blv[NT];
    #pragma unroll
    for (int nt = 0; nt < NT; nt++) {
        bhv[nt] = *(const u64*)(bph + (nt << 7));
        blv[nt] = *(const u64*)(bpl + (nt << 7));
    }
    const int lr = lane >> 2;
    const int lk = a_kof + (lane & 3) * 2;
    #pragma unroll
    for (int mt = 0; mt < 3; mt++) {
        int r = rb + mt * 16 + lr;
        u32 a0h = *(const u32*)(Ah + r * astr + lk);
        u32 a1h = *(const u32*)(Ah + (r + 8) * astr + lk);
        u32 a2h = *(const u32*)(Ah + r * astr + lk + 8);
        u32 a3h = *(const u32*)(Ah + (r + 8) * astr + lk + 8);
        u32 a0l = *(const u32*)(Al + r * astr + lk);
        u32 a1l = *(const u32*)(Al + (r + 8) * astr + lk);
        u32 a2l = *(const u32*)(Al + r * astr + lk + 8);
        u32 a3l = *(const u32*)(Al + (r + 8) * astr + lk + 8);
        #pragma unroll
        for (int nt = 0; nt < NT; nt++) {
            u32 b0 = (u32)bhv[nt], b1 = (u32)(bhv[nt] >> 32);
            u32 c0 = (u32)blv[nt], c1 = (u32)(blv[nt] >> 32);
            mma16816(acc[mt][nt], a0h, a1h, a2h, a3h, b0, b1);
            mma16816(acc[mt][nt], a0h, a1h, a2h, a3h, c0, c1);
            mma16816(acc[mt][nt], a0l, a1l, a2l, a3l, b0, b1);
        }
    }
}

// Single-pass readback: ALL warps dump D into full-width Hc, one sync, then all
// threads mix all columns (A-mix + bias(+relu)) and write next-layer bf16 A planes,
// or the fused mean/max epilogue on the final layer. 2 barriers total.
template<int NT, bool FINAL>
DEV void readback(unsigned char* smem, float acc[3][NT][4],
                  const float* Am, const float* __restrict__ bias,
                  float* __restrict__ out, long long obase,
                  int tid, int lane, int rg, int cbase)
{
    float* Hc = (float*)(smem + HC_OFF);
    u16* afh = (u16*)(smem + AF_HI);
    u16* afl = (u16*)(smem + AF_LO);
    const int lr = lane >> 2, q = lane & 3;
    #pragma unroll
    for (int mt = 0; mt < 3; mt++) {
        int r = rg * 48 + mt * 16 + lr;
        #pragma unroll
        for (int nt = 0; nt < NT; nt++) {
            int c = cbase + nt * 8 + q * 2;
            *(float2*)(Hc + r * HCSTR + c) = make_float2(acc[mt][nt][0], acc[mt][nt][1]);
            *(float2*)(Hc + (r + 8) * HCSTR + c) = make_float2(acc[mt][nt][2], acc[mt][nt][3]);
        }
    }
    __syncthreads();
    if (!FINAL) {
        #pragma unroll
        for (int s = 0; s < 4; s++) {
            int col = tid & 255;
            int b   = (tid >> 8) + 2 * s;
            float h[12];
            #pragma unroll
            for (int l = 0; l < 12; l++) h[l] = Hc[(b * 12 + l) * HCSTR + col];
            float bv = __ldg(bias + col);
            #pragma unroll
            for (int l = 0; l < 12; l++) {
                float a = 0.f;
                #pragma unroll
                for (int qq = NBR_OFF[l]; qq < NBR_OFF[l + 1]; qq++)
                    a += Am[l * 12 + NBR[qq]] * h[NBR[qq]];
                float y = fmaxf(a + bv, 0.f);
                int row = b * 12 + l;
                u16 hb = f2bf(y);
                afh[row * AFSTR + col] = hb;
                afl[row * AFSTR + col] = f2bf(y - bf2f(hb));
            }
        }
        __syncthreads();
    } else {
        #pragma unroll
        for (int s = 0; s < 2; s++) {
            int col = tid & 127;
            int b   = (tid >> 7) + 4 * s;
            float h[12];
            #pragma unroll
            for (int l = 0; l < 12; l++) h[l] = Hc[(b * 12 + l) * HCSTR + col];
            float bv = __ldg(bias + col);
            float sum = 0.f, mx = -3.402823466e38f;
            #pragma unroll
            for (int l = 0; l < 12; l++) {
                float a = 0.f;
                #pragma unroll
                for (int qq = NBR_OFF[l]; qq < NBR_OFF[l + 1]; qq++)
                    a += Am[l * 12 + NBR[qq]] * h[NBR[qq]];
                float y = a + bv;
                sum += y;
                mx = fmaxf(mx, y);
            }
            float* op = out + (obase + b) * 256;
            op[col]       = sum * (1.0f / 12.0f);
            op[128 + col] = mx;
        }
    }
}

__global__ void __launch_bounds__(THREADS, 1)
ecg_mma(const float* __restrict__ x,
        const float* __restrict__ b1, const float* __restrict__ b2,
        const float* __restrict__ b3, float* __restrict__ out)
{
    extern __shared__ unsigned char smem[];
    float* Am = (float*)(smem + AM_OFF);

    const int tid  = threadIdx.x;
    const int lane = tid & 31;
    const int w    = tid >> 5;       // 0..15
    const int rg   = w >> 3;         // 0..1 (M group)
    const int cg   = w & 7;          // 0..7 (N group)
    const int rb   = rg * 48;
    const int cb   = cg * 32;        // N=256 layers
    const int cb3  = cg * 16;        // N=128 layer
    const int lr   = lane >> 2;
    const int q    = lane & 3;
    const long long rowbase = (long long)blockIdx.x * MT;
    const long long obase   = (long long)blockIdx.x * BT;

    if (tid == 0) {
        float a[12][12];
        for (int i = 0; i < 12; i++)
            for (int j = 0; j < 12; j++) a[i][j] = (i == j) ? 2.0f : 0.0f;
        const int ei[15] = {0,0,1,0,1,2,0,1,1,2,6,7,8,9,10};
        const int ej[15] = {1,2,2,3,3,3,4,4,5,5,7,8,9,10,11};
        for (int e = 0; e < 15; e++) { a[ei[e]][ej[e]] = 1.0f; a[ej[e]][ei[e]] = 1.0f; }
        float dinv[12];
        for (int i = 0; i < 12; i++) {
            float s = 0.f;
            for (int j = 0; j < 12; j++) s += a[i][j];
            dinv[i] = 1.0f / sqrtf(s);
        }
        for (int i = 0; i < 12; i++)
            for (int j = 0; j < 12; j++)
                Am[i * 12 + j] = dinv[i] * a[i][j] * dinv[j];
    }

    // per-warp B fragment base offsets (u16 units): (cb + lr)*16 + 4q
    const u16* bph1 = g_w1h + ((cb  + lr) << 4) + (q << 2);
    const u16* bpl1 = g_w1l + ((cb  + lr) << 4) + (q << 2);
    const u16* bph2 = g_w2h + ((cb  + lr) << 4) + (q << 2);
    const u16* bpl2 = g_w2l + ((cb  + lr) << 4) + (q << 2);
    const u16* bph3 = g_w3h + ((cb3 + lr) << 4) + (q << 2);
    const u16* bpl3 = g_w3l + ((cb3 + lr) << 4) + (q << 2);
    constexpr int KSTEP256 = 256 * 16;   // u16 per 16-k chunk, N=256
    constexpr int KSTEP128 = 128 * 16;   // N=128

    // layer-1 A staging: row xr (active <96), k-quarter xq (8 floats each)
    const int xr = tid >> 2, xq = tid & 3;
    const bool xact = tid < MT * 4;

    u16* ashi[2] = {(u16*)(smem + 0),      (u16*)(smem + 2 * AS_SZ)};
    u16* aslo[2] = {(u16*)(smem + AS_SZ),  (u16*)(smem + 3 * AS_SZ)};

    float acc[3][4][4];
    #pragma unroll
    for (int i = 0; i < 3; i++)
        #pragma unroll
        for (int j = 0; j < 4; j++)
            #pragma unroll
            for (int v = 0; v < 4; v++) acc[i][j][v] = 0.f;

    // ---------------- Layer 1: X(96x512) @ W1 (K=512, 16 slabs of 32) ----------------
    {
        if (xact) {
            float4 v0 = *(const float4*)(x + (rowbase + xr) * 512 + xq * 8);
            float4 v1 = *(const float4*)(x + (rowbase + xr) * 512 + xq * 8 + 4);
            float vals[8] = {v0.x,v0.y,v0.z,v0.w, v1.x,v1.y,v1.z,v1.w};
            #pragma unroll
            for (int i = 0; i < 4; i++) {
                u32 hiw = pack_bf16(vals[2*i], vals[2*i+1]);
                *(u32*)(ashi[0] + xr * ASSTR + xq * 8 + 2 * i) = hiw;
                float r0 = bf2f((u16)(hiw & 0xFFFF));
                float r1 = bf2f((u16)(hiw >> 16));
                *(u32*)(aslo[0] + xr * ASSTR + xq * 8 + 2 * i) = pack_bf16(vals[2*i] - r0, vals[2*i+1] - r1);
            }
        }
        __syncthreads();

        for (int it = 0; it < 16; it++) {
            const int cur = it & 1, nxt = cur ^ 1;
            const bool more = it < 15;
            float4 v0, v1;
            if (more && xact) {
                v0 = *(const float4*)(x + (rowbase + xr) * 512 + (it + 1) * 32 + xq * 8);
                v1 = *(const float4*)(x + (rowbase + xr) * 512 + (it + 1) * 32 + xq * 8 + 4);
            }
            gemm_chunk<4>(ashi[cur], aslo[cur], ASSTR, 0, rb,
                          bph1 + (2 * it) * KSTEP256, bpl1 + (2 * it) * KSTEP256, acc, lane);
            gemm_chunk<4>(ashi[cur], aslo[cur], ASSTR, 16, rb,
                          bph1 + (2 * it + 1) * KSTEP256, bpl1 + (2 * it + 1) * KSTEP256, acc, lane);
            if (more && xact) {
                float vals[8] = {v0.x,v0.y,v0.z,v0.w, v1.x,v1.y,v1.z,v1.w};
                #pragma unroll
                for (int i = 0; i < 4; i++) {
                    u32 hiw = pack_bf16(vals[2*i], vals[2*i+1]);
                    *(u32*)(ashi[nxt] + xr * ASSTR + xq * 8 + 2 * i) = hiw;
                    float r0 = bf2f((u16)(hiw & 0xFFFF));
                    float r1 = bf2f((u16)(hiw >> 16));
                    *(u32*)(aslo[nxt] + xr * ASSTR + xq * 8 + 2 * i) = pack_bf16(vals[2*i] - r0, vals[2*i+1] - r1);
                }
            }
            __syncthreads();
        }
    }
    readback<4, false>(smem, acc, Am, b1, out, obase, tid, lane, rg, cb);

    // ---------------- Layer 2: H1(96x256) @ W2 (K=256, 16 chunks, NO barriers) ----------------
    #pragma unroll
    for (int i = 0; i < 3; i++)
        #pragma unroll
        for (int j = 0; j < 4; j++)
            #pragma unroll
            for (int v = 0; v < 4; v++) acc[i][j][v] = 0.f;
    {
        u16* afh = (u16*)(smem + AF_HI);
        u16* afl = (u16*)(smem + AF_LO);
        #pragma unroll 2
        for (int kc = 0; kc < 16; kc++)
            gemm_chunk<4>(afh, afl, AFSTR, kc * 16, rb,
                          bph2 + kc * KSTEP256, bpl2 + kc * KSTEP256, acc, lane);
    }
    readback<4, false>(smem, acc, Am, b2, out, obase, tid, lane, rg, cb);

    // ---------------- Layer 3: H2(96x256) @ W3 (K=256, 16 chunks, N=128, NO barriers) ----------------
    float acc3[3][2][4];
    #pragma unroll
    for (int i = 0; i < 3; i++)
        #pragma unroll
        for (int j = 0; j < 2; j++)
            #pragma unroll
            for (int v = 0; v < 4; v++) acc3[i][j][v] = 0.f;
    {
        u16* afh = (u16*)(smem + AF_HI);
        u16* afl = (u16*)(smem + AF_LO);
        #pragma unroll 2
        for (int kc = 0; kc < 16; kc++)
            gemm_chunk<2>(afh, afl, AFSTR, kc * 16, rb,
                          bph3 + kc * KSTEP128, bpl3 + kc * KSTEP128, acc3, lane);
    }
    readback<2, true>(smem, acc3, Am, b3, out, obase, tid, lane, rg, cb3);
}

extern "C" void kernel_launch(void* const* d_in, const int* in_sizes, int n_in,
                              void* d_out, int out_size)
{
    const float* x  = (const float*)d_in[0];
    const float* W1 = (const float*)d_in[1];
    const float* b1 = (const float*)d_in[2];
    const float* W2 = (const float*)d_in[3];
    const float* b2 = (const float*)d_in[4];
    const float* W3 = (const float*)d_in[5];
    const float* b3 = (const float*)d_in[6];
    float* out = (float*)d_out;

    conv_w<<<148, 512>>>(W1, W2, W3);

    cudaFuncSetAttribute(ecg_mma, cudaFuncAttributeMaxDynamicSharedMemorySize, SMEM_BYTES);
    ecg_mma<<<BATCH / BT, THREADS, SMEM_BYTES>>>(x, b1, b2, b3, out);
}